// round 2
// baseline (speedup 1.0000x reference)
#include <cuda_runtime.h>
#include <cstdint>

#define NHEADS   32
#define HEAD     128
#define KVHEADS  8
#define SEQ      2048
#define BATCH    2
#define WINDOW   1024
#define SCALEF   0.08838834764831845f

#define BQ       64     // queries per CTA
#define BK       64     // keys per tile
#define THREADS  256
#define RPW      8      // query rows per warp

// smem: Q tile (BQ x 128) + K tile (BK x 128, swizzled) + V tile (BK x 128, swizzled)
#define SMEM_FLOATS ((BQ + BK + BK) * HEAD)
#define SMEM_BYTES  (SMEM_FLOATS * 4)

__global__ void __launch_bounds__(THREADS)
attn_swa_kernel(const float* __restrict__ qg_,
                const float* __restrict__ kg_,
                const float* __restrict__ vg_,
                float* __restrict__ out)
{
    extern __shared__ float smem[];
    float* qs = smem;                  // BQ*128, linear
    float* ks = smem + BQ * HEAD;      // BK*128, chunk-swizzled
    float* vs = ks + BK * HEAD;        // BK*128, chunk-swizzled

    const int tid  = threadIdx.x;
    const int warp = tid >> 5;
    const int lane = tid & 31;
    const int q0   = blockIdx.x * BQ;
    const int h    = blockIdx.y;
    const int b    = blockIdx.z;
    const int kvh  = h >> 2;           // GROUP = NHEADS/KVHEADS = 4

    const float* qg = qg_ + (size_t)b * SEQ * (NHEADS * HEAD) + h * HEAD;
    const float* kg = kg_ + (size_t)b * SEQ * (KVHEADS * HEAD) + kvh * HEAD;
    const float* vg = vg_ + (size_t)b * SEQ * (KVHEADS * HEAD) + kvh * HEAD;

    // ---- load Q tile, pre-scaled by SCALE * log2(e) so we can use exp2f ----
    const float qscale = SCALEF * 1.4426950408889634f;
    for (int idx = tid; idx < BQ * 32; idx += THREADS) {
        int row = idx >> 5, c = idx & 31;
        float4 val = *(const float4*)(qg + (size_t)(q0 + row) * (NHEADS * HEAD) + c * 4);
        val.x *= qscale; val.y *= qscale; val.z *= qscale; val.w *= qscale;
        ((float4*)qs)[row * 32 + c] = val;
    }

    float acc[RPW][4];
    float mrow[RPW], lrow[RPW];
#pragma unroll
    for (int r = 0; r < RPW; r++) {
        mrow[r] = -1e30f; lrow[r] = 0.f;
        acc[r][0] = acc[r][1] = acc[r][2] = acc[r][3] = 0.f;
    }

    // key-tile range: covers [max(0, q0-1023), q0+63], 64-aligned
    const int t_lo = (q0 >= WINDOW) ? (q0 - WINDOW) : 0;

    for (int ts = t_lo; ts <= q0; ts += BK) {
        __syncthreads();
        // ---- load K/V tiles with per-row chunk swizzle (bank-conflict free) ----
        for (int idx = tid; idx < BK * 32; idx += THREADS) {
            int row = idx >> 5, c = idx & 31;
            int sc = c ^ (row & 31);
            const size_t goff = (size_t)(ts + row) * (KVHEADS * HEAD) + c * 4;
            ((float4*)ks)[row * 32 + sc] = *(const float4*)(kg + goff);
            ((float4*)vs)[row * 32 + sc] = *(const float4*)(vg + goff);
        }
        __syncthreads();

        // ---- QK: lane owns keys (ts+lane) and (ts+32+lane) for all 8 rows ----
        float s0[RPW], s1[RPW];
#pragma unroll
        for (int r = 0; r < RPW; r++) { s0[r] = 0.f; s1[r] = 0.f; }

#pragma unroll 8
        for (int c = 0; c < 32; ++c) {
            float4 k0 = ((const float4*)ks)[lane * 32 + (c ^ lane)];
            float4 k1 = ((const float4*)ks)[(lane + 32) * 32 + (c ^ lane)];
#pragma unroll
            for (int r = 0; r < RPW; r++) {
                float4 qv = ((const float4*)qs)[(warp * RPW + r) * 32 + c];
                s0[r] += qv.x * k0.x + qv.y * k0.y + qv.z * k0.z + qv.w * k0.w;
                s1[r] += qv.x * k1.x + qv.y * k1.y + qv.z * k1.z + qv.w * k1.w;
            }
        }

        // ---- online softmax update ----
        const int ka = ts + lane, kb = ts + 32 + lane;
#pragma unroll
        for (int r = 0; r < RPW; r++) {
            const int qa = q0 + warp * RPW + r;
            const bool va = (ka <= qa) && (qa - ka < WINDOW);
            const bool vb = (kb <= qa) && (qa - kb < WINDOW);
            float x0 = va ? s0[r] : -1e30f;
            float x1 = vb ? s1[r] : -1e30f;
            float tmax = fmaxf(x0, x1);
#pragma unroll
            for (int o = 16; o; o >>= 1)
                tmax = fmaxf(tmax, __shfl_xor_sync(0xffffffffu, tmax, o));
            const float mn = fmaxf(mrow[r], tmax);
            // exact-0 wipe of any bogus fully-masked-tile contributions:
            // mrow=-1e30, mn finite -> exp2f(-1e30) == 0
            const float alpha = exp2f(mrow[r] - mn);
            mrow[r] = mn;
            float p0 = exp2f(x0 - mn);
            float p1 = exp2f(x1 - mn);
            float psum = p0 + p1;
#pragma unroll
            for (int o = 16; o; o >>= 1)
                psum += __shfl_xor_sync(0xffffffffu, psum, o);
            lrow[r] = lrow[r] * alpha + psum;
            acc[r][0] *= alpha; acc[r][1] *= alpha;
            acc[r][2] *= alpha; acc[r][3] *= alpha;
            s0[r] = p0; s1[r] = p1;   // reuse as probabilities
        }

        // ---- PV: broadcast p via shfl; lane owns dims [lane*4, lane*4+4) ----
#pragma unroll 4
        for (int i = 0; i < 32; ++i) {
            float4 vv = ((const float4*)vs)[i * 32 + (lane ^ i)];
#pragma unroll
            for (int r = 0; r < RPW; r++) {
                float pj = __shfl_sync(0xffffffffu, s0[r], i);
                acc[r][0] += pj * vv.x; acc[r][1] += pj * vv.y;
                acc[r][2] += pj * vv.z; acc[r][3] += pj * vv.w;
            }
        }
#pragma unroll 4
        for (int i = 0; i < 32; ++i) {
            float4 vv = ((const float4*)vs)[(i + 32) * 32 + (lane ^ i)];
#pragma unroll
            for (int r = 0; r < RPW; r++) {
                float pj = __shfl_sync(0xffffffffu, s1[r], i);
                acc[r][0] += pj * vv.x; acc[r][1] += pj * vv.y;
                acc[r][2] += pj * vv.z; acc[r][3] += pj * vv.w;
            }
        }
    }

    // ---- epilogue: normalize + store ----
#pragma unroll
    for (int r = 0; r < RPW; r++) {
        const int qa = q0 + warp * RPW + r;
        const float inv = 1.0f / lrow[r];
        float4 o;
        o.x = acc[r][0] * inv; o.y = acc[r][1] * inv;
        o.z = acc[r][2] * inv; o.w = acc[r][3] * inv;
        *(float4*)(out + ((size_t)b * SEQ + qa) * (NHEADS * HEAD) + h * HEAD + lane * 4) = o;
    }
}

extern "C" void kernel_launch(void* const* d_in, const int* in_sizes, int n_in,
                              void* d_out, int out_size)
{
    const float* q = (const float*)d_in[0];
    const float* k = (const float*)d_in[1];
    const float* v = (const float*)d_in[2];
    float* out = (float*)d_out;

    cudaFuncSetAttribute(attn_swa_kernel,
                         cudaFuncAttributeMaxDynamicSharedMemorySize, SMEM_BYTES);
    dim3 grid(SEQ / BQ, NHEADS, BATCH);
    attn_swa_kernel<<<grid, THREADS, SMEM_BYTES>>>(q, k, v, out);
}

// round 8
// speedup vs baseline: 3.4701x; 3.4701x over previous
#include <cuda_runtime.h>
#include <cstdint>

#define NHEADS 32
#define HEAD 128
#define KVHEADS 8
#define SEQ 2048
#define BATCH 2
#define WINDOW 1024
#define SCALEF 0.08838834764831845f
#define LOG2E 1.4426950408889634f

#define BQ 128
#define BK 64
#define THREADS 256

// smem staging (all row-major with per-row XOR swizzle on 16B granules)
#define OFF_Q 0                        // 128 rows x 128 tf32 (512B/row)  = 65536
#define OFF_K (BQ * HEAD * 4)          // 64 keys x 128 tf32              = 32768
#define OFF_V (OFF_K + BK * HEAD * 4)  // 64 keys x 128 tf32              = 32768
#define OFF_P (OFF_V + BK * HEAD * 4)  // 128 rows x 64 tf32 (256B/row)   = 32768
#define SMEM_BYTES (OFF_P + BQ * BK * 4)

static __device__ __forceinline__ uint32_t cvt_tf32(float x){
    uint32_t r; asm("cvt.rna.tf32.f32 %0, %1;" : "=r"(r) : "f"(x)); return r;
}
static __device__ __forceinline__ float ex2f(float x){
    float y; asm("ex2.approx.f32 %0, %1;" : "=f"(y) : "f"(x)); return y;
}
#define MMA(d, a0, a1, a2, a3, b0, b1) \
    asm volatile("mma.sync.aligned.m16n8k8.row.col.f32.tf32.tf32.f32 " \
        "{%0,%1,%2,%3}, {%4,%5,%6,%7}, {%8,%9}, {%0,%1,%2,%3};" \
        : "+f"((d)[0]), "+f"((d)[1]), "+f"((d)[2]), "+f"((d)[3]) \
        : "r"(a0), "r"(a1), "r"(a2), "r"(a3), "r"(b0), "r"(b1))

__global__ void __launch_bounds__(THREADS, 1)
attn_mma(const float* __restrict__ qg_, const float* __restrict__ kg_,
         const float* __restrict__ vg_, float* __restrict__ out)
{
    extern __shared__ char sm[];
    const int tid = threadIdx.x, w = tid >> 5, l = tid & 31;
    const int g = l >> 2, t = l & 3;
    const int q0 = blockIdx.x * BQ, h = blockIdx.y, b = blockIdx.z;
    const int kvh = h >> 2;

    const float* qg = qg_ + (size_t)b * SEQ * (NHEADS * HEAD) + (size_t)h * HEAD;
    const float* kg = kg_ + (size_t)b * SEQ * (KVHEADS * HEAD) + (size_t)kvh * HEAD;
    const float* vg = vg_ + (size_t)b * SEQ * (KVHEADS * HEAD) + (size_t)kvh * HEAD;

    // ---- stage Q (warp-local 16 rows), pre-scaled, tf32, swizzle ^(row&7) ----
    const float qsc = SCALEF * LOG2E;
#pragma unroll
    for (int j = 0; j < 16; j++){
        const int row = w * 16 + j;
        const float4 v = *(const float4*)(qg + (size_t)(q0 + row) * (NHEADS * HEAD) + l * 4);
        uint4 u;
        u.x = cvt_tf32(v.x * qsc); u.y = cvt_tf32(v.y * qsc);
        u.z = cvt_tf32(v.z * qsc); u.w = cvt_tf32(v.w * qsc);
        *(uint4*)(sm + OFF_Q + row * 512 + ((l ^ (row & 7)) << 4)) = u;
    }

    float o[16][4];
#pragma unroll
    for (int n = 0; n < 16; n++){ o[n][0] = o[n][1] = o[n][2] = o[n][3] = 0.f; }
    float m0 = -1e30f, m1 = -1e30f, l0 = 0.f, l1 = 0.f;
    const int r0 = q0 + w * 16 + g, r1 = r0 + 8;
    const int sp = 2 * (g & 3) + (g >> 2);   // P-row swizzle for own rows

    int t_lo = 0;
    if (q0 >= WINDOW) t_lo = ((q0 - WINDOW + 1) >> 6) << 6;

    for (int ts = t_lo; ts <= q0 + BK; ts += BK){
        __syncthreads();
        // ---- stage K/V tiles (tf32, swizzled) ----
#pragma unroll
        for (int it = 0; it < 8; it++){
            const int key = w + it * 8;
            const size_t go = (size_t)(ts + key) * (KVHEADS * HEAD) + l * 4;
            const float4 kv = *(const float4*)(kg + go);
            uint4 ku;
            ku.x = cvt_tf32(kv.x); ku.y = cvt_tf32(kv.y);
            ku.z = cvt_tf32(kv.z); ku.w = cvt_tf32(kv.w);
            *(uint4*)(sm + OFF_K + key * 512 + ((l ^ (key & 7)) << 4)) = ku;
            const float4 vv = *(const float4*)(vg + go);
            uint4 vu;
            vu.x = cvt_tf32(vv.x); vu.y = cvt_tf32(vv.y);
            vu.z = cvt_tf32(vv.z); vu.w = cvt_tf32(vv.w);
            const int svz = 2 * (key & 3) + ((key >> 2) & 1);
            *(uint4*)(sm + OFF_V + key * 512 + ((l ^ svz) << 4)) = vu;
        }
        __syncthreads();

        // ---- GEMM1: S(16x64 per warp) = Q @ K^T ----
        float s[8][4];
#pragma unroll
        for (int n = 0; n < 8; n++){ s[n][0] = s[n][1] = s[n][2] = s[n][3] = 0.f; }
        {
            const char* qb = sm + OFF_Q + (w * 16 + g) * 512 + t * 4;
#pragma unroll
            for (int kc = 0; kc < 16; kc++){
                const uint32_t a0 = *(const uint32_t*)(qb + (((2*kc  ) ^ g) << 4));
                const uint32_t a1 = *(const uint32_t*)(qb + 4096 + (((2*kc  ) ^ g) << 4));
                const uint32_t a2 = *(const uint32_t*)(qb + (((2*kc+1) ^ g) << 4));
                const uint32_t a3 = *(const uint32_t*)(qb + 4096 + (((2*kc+1) ^ g) << 4));
#pragma unroll
                for (int n = 0; n < 8; n++){
                    const char* kb = sm + OFF_K + n * 4096 + g * 512 + t * 4;
                    const uint32_t b0 = *(const uint32_t*)(kb + (((2*kc  ) ^ g) << 4));
                    const uint32_t b1 = *(const uint32_t*)(kb + (((2*kc+1) ^ g) << 4));
                    MMA(s[n], a0, a1, a2, a3, b0, b1);
                }
            }
        }

        // ---- mask + online softmax (rows r0, r1 live in this warp's 4-lane group) ----
        float mx0 = -1e30f, mx1 = -1e30f;
#pragma unroll
        for (int n = 0; n < 8; n++){
            const int c0 = ts + n * 8 + 2 * t, c1 = c0 + 1;
            s[n][0] = ((c0 <= r0) && (r0 - c0 < WINDOW)) ? s[n][0] : -1e30f;
            s[n][1] = ((c1 <= r0) && (r0 - c1 < WINDOW)) ? s[n][1] : -1e30f;
            s[n][2] = ((c0 <= r1) && (r1 - c0 < WINDOW)) ? s[n][2] : -1e30f;
            s[n][3] = ((c1 <= r1) && (r1 - c1 < WINDOW)) ? s[n][3] : -1e30f;
            mx0 = fmaxf(mx0, fmaxf(s[n][0], s[n][1]));
            mx1 = fmaxf(mx1, fmaxf(s[n][2], s[n][3]));
        }
        mx0 = fmaxf(mx0, __shfl_xor_sync(0xffffffffu, mx0, 1));
        mx0 = fmaxf(mx0, __shfl_xor_sync(0xffffffffu, mx0, 2));
        mx1 = fmaxf(mx1, __shfl_xor_sync(0xffffffffu, mx1, 1));
        mx1 = fmaxf(mx1, __shfl_xor_sync(0xffffffffu, mx1, 2));

        const float mn0 = fmaxf(m0, mx0), mn1 = fmaxf(m1, mx1);
        const float mc0 = fmaxf(mn0, -1e29f), mc1 = fmaxf(mn1, -1e29f);
        const float al0 = ex2f(m0 - mc0), al1 = ex2f(m1 - mc1);
        m0 = mn0; m1 = mn1;

        float ps0 = 0.f, ps1 = 0.f;
        {
            char* p0 = sm + OFF_P + (w * 16 + g) * 256 + (t & 1) * 8;
            char* p1 = p0 + 8 * 256;
#pragma unroll
            for (int n = 0; n < 8; n++){
                uint2 u0, u1;
                u0.x = cvt_tf32(ex2f(s[n][0] - mc0));
                u0.y = cvt_tf32(ex2f(s[n][1] - mc0));
                u1.x = cvt_tf32(ex2f(s[n][2] - mc1));
                u1.y = cvt_tf32(ex2f(s[n][3] - mc1));
                ps0 += __uint_as_float(u0.x) + __uint_as_float(u0.y);
                ps1 += __uint_as_float(u1.x) + __uint_as_float(u1.y);
                const int gr = (2 * n + (t >> 1)) ^ sp;
                *(uint2*)(p0 + (gr << 4)) = u0;
                *(uint2*)(p1 + (gr << 4)) = u1;
            }
        }
        ps0 += __shfl_xor_sync(0xffffffffu, ps0, 1);
        ps0 += __shfl_xor_sync(0xffffffffu, ps0, 2);
        ps1 += __shfl_xor_sync(0xffffffffu, ps1, 1);
        ps1 += __shfl_xor_sync(0xffffffffu, ps1, 2);
        l0 = l0 * al0 + ps0;
        l1 = l1 * al1 + ps1;

#pragma unroll
        for (int n = 0; n < 16; n++){
            o[n][0] *= al0; o[n][1] *= al0; o[n][2] *= al1; o[n][3] *= al1;
        }
        __syncwarp();

        // ---- GEMM2: O(16x128 per warp) += P @ V ----
        {
            const char* pb = sm + OFF_P + (w * 16 + g) * 256 + t * 4;
#pragma unroll
            for (int kc = 0; kc < 8; kc++){
                const uint32_t a0 = *(const uint32_t*)(pb + (((2*kc  ) ^ sp) << 4));
                const uint32_t a1 = *(const uint32_t*)(pb + 2048 + (((2*kc  ) ^ sp) << 4));
                const uint32_t a2 = *(const uint32_t*)(pb + (((2*kc+1) ^ sp) << 4));
                const uint32_t a3 = *(const uint32_t*)(pb + 2048 + (((2*kc+1) ^ sp) << 4));
                const char* vb = sm + OFF_V + (kc * 8 + t) * 512 + (g & 3) * 4;
#pragma unroll
                for (int n = 0; n < 16; n++){
                    const uint32_t b0 = *(const uint32_t*)(vb + (((2*n + (g>>2)) ^ (2*t  )) << 4));
                    const uint32_t b1 = *(const uint32_t*)(vb + 2048 + (((2*n + (g>>2)) ^ (2*t+1)) << 4));
                    MMA(o[n], a0, a1, a2, a3, b0, b1);
                }
            }
        }
    }

    // ---- epilogue: normalize + store ----
    const float i0 = 1.f / l0, i1 = 1.f / l1;
    float* op0 = out + ((size_t)b * SEQ + r0) * (NHEADS * HEAD) + h * HEAD + 2 * t;
    float* op1 = out + ((size_t)b * SEQ + r1) * (NHEADS * HEAD) + h * HEAD + 2 * t;
#pragma unroll
    for (int n = 0; n < 16; n++){
        float2 v0; v0.x = o[n][0] * i0; v0.y = o[n][1] * i0;
        float2 v1; v1.x = o[n][2] * i1; v1.y = o[n][3] * i1;
        *(float2*)(op0 + n * 8) = v0;
        *(float2*)(op1 + n * 8) = v1;
    }
}

extern "C" void kernel_launch(void* const* d_in, const int* in_sizes, int n_in,
                              void* d_out, int out_size)
{
    const float* q = (const float*)d_in[0];
    const float* k = (const float*)d_in[1];
    const float* v = (const float*)d_in[2];
    float* out = (float*)d_out;

    cudaFuncSetAttribute(attn_mma, cudaFuncAttributeMaxDynamicSharedMemorySize, SMEM_BYTES);
    dim3 grid(SEQ / BQ, NHEADS, BATCH);
    attn_mma<<<grid, THREADS, SMEM_BYTES>>>(q, k, v, out);
}

// round 12
// speedup vs baseline: 3.8397x; 1.1065x over previous
#include <cuda_runtime.h>
#include <cuda_fp16.h>
#include <cstdint>

#define NHEADS 32
#define HEAD 128
#define KVHEADS 8
#define SEQ 2048
#define BATCH 2
#define WINDOW 1024
#define SCALEF 0.08838834764831845f
#define LOG2E 1.4426950408889634f

#define BQ 128
#define BK 64
#define THREADS 256

// fp16 tiles in "paired" chunk layout: each 32B chunk = 16 elems of one row,
// pair j (8B) = {e[16c+2j], e[16c+2j+1], e[16c+2j+8], e[16c+2j+9]}  (j=0..3)
// -> every m16n8k16 fragment load is ONE conflict-free LDS.64.
#define OFF_Q 0        // Q : 128 rows x 128 dims f16, 256B/row = 32768
#define OFF_K 32768    // K : 64 keys  x 128 dims f16, 256B/row = 16384
#define OFF_V 49152    // V^T: 128 dims x 64 keys f16, 128B/row = 16384
#define SMEM_BYTES 65536

static __device__ __forceinline__ uint32_t pk(float x, float y){
    __half2 h = __floats2half2_rn(x, y);
    return *(uint32_t*)&h;
}
static __device__ __forceinline__ float ex2f(float x){
    float y; asm("ex2.approx.f32 %0, %1;" : "=f"(y) : "f"(x)); return y;
}
#define MMA16(d, a0, a1, a2, a3, b0, b1) \
    asm volatile("mma.sync.aligned.m16n8k16.row.col.f32.f16.f16.f32 " \
        "{%0,%1,%2,%3}, {%4,%5,%6,%7}, {%8,%9}, {%0,%1,%2,%3};" \
        : "+f"((d)[0]), "+f"((d)[1]), "+f"((d)[2]), "+f"((d)[3]) \
        : "r"(a0), "r"(a1), "r"(a2), "r"(a3), "r"(b0), "r"(b1))

__global__ void __launch_bounds__(THREADS, 1)
attn_h16(const float* __restrict__ qg_, const float* __restrict__ kg_,
         const float* __restrict__ vg_, float* __restrict__ out)
{
    extern __shared__ char sm[];
    const int tid = threadIdx.x, w = tid >> 5, l = tid & 31;
    const int g = l >> 2, t = l & 3;
    const int q0 = blockIdx.x * BQ, h = blockIdx.y, b = blockIdx.z;
    const int kvh = h >> 2;

    const float* qg = qg_ + (size_t)b * SEQ * (NHEADS * HEAD) + (size_t)h * HEAD;
    const float* kg = kg_ + (size_t)b * SEQ * (KVHEADS * HEAD) + (size_t)kvh * HEAD;
    const float* vg = vg_ + (size_t)b * SEQ * (KVHEADS * HEAD) + (size_t)kvh * HEAD;

    // ---- stage Q: pre-scaled, f16, paired layout, chunk-swizzled ----
    const float qsc = SCALEF * LOG2E;
#pragma unroll
    for (int i = tid; i < BQ * 8; i += THREADS){
        const int row = i >> 3, kc = i & 7;
        const float* gp = qg + (size_t)(q0 + row) * (NHEADS * HEAD) + kc * 16;
        float4 f0 = *(const float4*)(gp);
        float4 f1 = *(const float4*)(gp + 4);
        float4 f2 = *(const float4*)(gp + 8);
        float4 f3 = *(const float4*)(gp + 12);
        char* spp = sm + OFF_Q + row * 256 + ((kc ^ (row & 7)) << 5);
        uint4 u1, u2;
        u1.x = pk(f0.x * qsc, f0.y * qsc); u1.y = pk(f2.x * qsc, f2.y * qsc);
        u1.z = pk(f0.z * qsc, f0.w * qsc); u1.w = pk(f2.z * qsc, f2.w * qsc);
        u2.x = pk(f1.x * qsc, f1.y * qsc); u2.y = pk(f3.x * qsc, f3.y * qsc);
        u2.z = pk(f1.z * qsc, f1.w * qsc); u2.w = pk(f3.z * qsc, f3.w * qsc);
        *(uint4*)spp = u1; *(uint4*)(spp + 16) = u2;
    }

    float o[16][4];
#pragma unroll
    for (int n = 0; n < 16; n++){ o[n][0] = o[n][1] = o[n][2] = o[n][3] = 0.f; }
    float m0 = -1e30f, m1 = -1e30f, l0 = 0.f, l1 = 0.f;
    const int r0 = q0 + w * 16 + g, r1 = r0 + 8;

    int t_lo = 0;
    if (q0 >= WINDOW) t_lo = ((q0 - WINDOW + 1) >> 6) << 6;

    for (int ts = t_lo; ts <= q0 + BK; ts += BK){
        __syncthreads();
        // ---- stage K (paired layout, 2 chunk-tasks/thread) ----
#pragma unroll
        for (int i = tid; i < BK * 8; i += THREADS){
            const int row = i >> 3, kc = i & 7;
            const float* gp = kg + (size_t)(ts + row) * (KVHEADS * HEAD) + kc * 16;
            float4 f0 = *(const float4*)(gp);
            float4 f1 = *(const float4*)(gp + 4);
            float4 f2 = *(const float4*)(gp + 8);
            float4 f3 = *(const float4*)(gp + 12);
            char* spp = sm + OFF_K + row * 256 + ((kc ^ (row & 7)) << 5);
            uint4 u1, u2;
            u1.x = pk(f0.x, f0.y); u1.y = pk(f2.x, f2.y);
            u1.z = pk(f0.z, f0.w); u1.w = pk(f2.z, f2.w);
            u2.x = pk(f1.x, f1.y); u2.y = pk(f3.x, f3.y);
            u2.z = pk(f1.z, f1.w); u2.w = pk(f3.z, f3.w);
            *(uint4*)spp = u1; *(uint4*)(spp + 16) = u2;
        }
        // ---- stage V transposed (dims-major), paired over keys ----
#pragma unroll
        for (int i = tid; i < 32 * 32; i += THREADS){
            const int kp = i & 31, dg = i >> 5;   // key pair, dim group of 4
            const float* va = vg + (size_t)(ts + 2 * kp) * (KVHEADS * HEAD) + dg * 4;
            const float4 a = *(const float4*)va;
            const float4 c = *(const float4*)(va + KVHEADS * HEAD);
            const int kc = kp >> 3, base = (kp & 3) * 8 + ((kp >> 2) & 1) * 4;
            const int d0 = dg * 4;
            *(uint32_t*)(sm + OFF_V + (d0    ) * 128 + ((kc ^ ((d0    ) & 3)) << 5) + base) = pk(a.x, c.x);
            *(uint32_t*)(sm + OFF_V + (d0 + 1) * 128 + ((kc ^ ((d0 + 1) & 3)) << 5) + base) = pk(a.y, c.y);
            *(uint32_t*)(sm + OFF_V + (d0 + 2) * 128 + ((kc ^ ((d0 + 2) & 3)) << 5) + base) = pk(a.z, c.z);
            *(uint32_t*)(sm + OFF_V + (d0 + 3) * 128 + ((kc ^ ((d0 + 3) & 3)) << 5) + base) = pk(a.w, c.w);
        }
        __syncthreads();

        // ---- GEMM1: S(16x64 per warp) = Q @ K^T, fp16 k16 ----
        float s[8][4];
#pragma unroll
        for (int n = 0; n < 8; n++){ s[n][0] = s[n][1] = s[n][2] = s[n][3] = 0.f; }
        {
            const char* qb = sm + OFF_Q + (w * 16 + g) * 256 + t * 8;
            const char* kb = sm + OFF_K + g * 256 + t * 8;
#pragma unroll
            for (int kc = 0; kc < 8; kc++){
                const int co = (kc ^ g) << 5;
                const uint2 A02 = *(const uint2*)(qb + co);            // a0,a2 (rows g)
                const uint2 A13 = *(const uint2*)(qb + 2048 + co);     // a1,a3 (rows g+8)
#pragma unroll
                for (int n = 0; n < 8; n++){
                    const uint2 B = *(const uint2*)(kb + n * 2048 + co);
                    MMA16(s[n], A02.x, A13.x, A02.y, A13.y, B.x, B.y);
                }
            }
        }

        // ---- mask + online softmax (warp-local rows) ----
        float mx0 = -1e30f, mx1 = -1e30f;
#pragma unroll
        for (int n = 0; n < 8; n++){
            const int c0 = ts + n * 8 + 2 * t, c1 = c0 + 1;
            s[n][0] = ((c0 <= r0) && (r0 - c0 < WINDOW)) ? s[n][0] : -1e30f;
            s[n][1] = ((c1 <= r0) && (r0 - c1 < WINDOW)) ? s[n][1] : -1e30f;
            s[n][2] = ((c0 <= r1) && (r1 - c0 < WINDOW)) ? s[n][2] : -1e30f;
            s[n][3] = ((c1 <= r1) && (r1 - c1 < WINDOW)) ? s[n][3] : -1e30f;
            mx0 = fmaxf(mx0, fmaxf(s[n][0], s[n][1]));
            mx1 = fmaxf(mx1, fmaxf(s[n][2], s[n][3]));
        }
        mx0 = fmaxf(mx0, __shfl_xor_sync(0xffffffffu, mx0, 1));
        mx0 = fmaxf(mx0, __shfl_xor_sync(0xffffffffu, mx0, 2));
        mx1 = fmaxf(mx1, __shfl_xor_sync(0xffffffffu, mx1, 1));
        mx1 = fmaxf(mx1, __shfl_xor_sync(0xffffffffu, mx1, 2));

        const float mn0 = fmaxf(m0, mx0), mn1 = fmaxf(m1, mx1);
        const float mc0 = fmaxf(mn0, -1e29f), mc1 = fmaxf(mn1, -1e29f);
        const float al0 = ex2f(m0 - mc0), al1 = ex2f(m1 - mc1);
        m0 = mn0; m1 = mn1;

        // P stays in registers: GEMM1 C-fragment == GEMM2 A-fragment (packed f16x2)
        uint32_t ph[8][2];
        float ps0 = 0.f, ps1 = 0.f;
#pragma unroll
        for (int n = 0; n < 8; n++){
            ph[n][0] = pk(ex2f(s[n][0] - mc0), ex2f(s[n][1] - mc0));
            ph[n][1] = pk(ex2f(s[n][2] - mc1), ex2f(s[n][3] - mc1));
            const float2 f0 = __half22float2(*(__half2*)&ph[n][0]);
            const float2 f1 = __half22float2(*(__half2*)&ph[n][1]);
            ps0 += f0.x + f0.y;
            ps1 += f1.x + f1.y;
        }
        ps0 += __shfl_xor_sync(0xffffffffu, ps0, 1);
        ps0 += __shfl_xor_sync(0xffffffffu, ps0, 2);
        ps1 += __shfl_xor_sync(0xffffffffu, ps1, 1);
        ps1 += __shfl_xor_sync(0xffffffffu, ps1, 2);
        l0 = l0 * al0 + ps0;
        l1 = l1 * al1 + ps1;

#pragma unroll
        for (int n = 0; n < 16; n++){
            o[n][0] *= al0; o[n][1] *= al0; o[n][2] *= al1; o[n][3] *= al1;
        }

        // ---- GEMM2: O(16x128 per warp) += P @ V ----
        {
            const char* vb = sm + OFF_V + g * 128 + t * 8;
            const int co = (g & 3);
#pragma unroll
            for (int kc = 0; kc < 4; kc++){
                const uint32_t a0 = ph[2 * kc][0],     a1 = ph[2 * kc][1];
                const uint32_t a2 = ph[2 * kc + 1][0], a3 = ph[2 * kc + 1][1];
                const int cs = (kc ^ co) << 5;
#pragma unroll
                for (int n = 0; n < 16; n++){
                    const uint2 B = *(const uint2*)(vb + n * 1024 + cs);
                    MMA16(o[n], a0, a1, a2, a3, B.x, B.y);
                }
            }
        }
    }

    // ---- epilogue: normalize + store ----
    const float i0 = 1.f / l0, i1 = 1.f / l1;
    float* op0 = out + ((size_t)b * SEQ + r0) * (NHEADS * HEAD) + h * HEAD + 2 * t;
    float* op1 = out + ((size_t)b * SEQ + r1) * (NHEADS * HEAD) + h * HEAD + 2 * t;
#pragma unroll
    for (int n = 0; n < 16; n++){
        float2 v0; v0.x = o[n][0] * i0; v0.y = o[n][1] * i0;
        float2 v1; v1.x = o[n][2] * i1; v1.y = o[n][3] * i1;
        *(float2*)(op0 + n * 8) = v0;
        *(float2*)(op1 + n * 8) = v1;
    }
}

extern "C" void kernel_launch(void* const* d_in, const int* in_sizes, int n_in,
                              void* d_out, int out_size)
{
    const float* q = (const float*)d_in[0];
    const float* k = (const float*)d_in[1];
    const float* v = (const float*)d_in[2];
    float* out = (float*)d_out;

    cudaFuncSetAttribute(attn_h16, cudaFuncAttributeMaxDynamicSharedMemorySize, SMEM_BYTES);
    dim3 grid(SEQ / BQ, NHEADS, BATCH);
    attn_h16<<<grid, THREADS, SMEM_BYTES>>>(q, k, v, out);
}